// round 14
// baseline (speedup 1.0000x reference)
#include <cuda_runtime.h>
#include <cstdint>

#define Nn 50000
#define Ee 800000
#define Gg 512
#define NBLK 196          // ceil(Nn/256)
#define PROJ_BX 391       // ceil(Nn/128)
#define PROJ_TILES 782    // PROJ_BX * 2
#define PROJ_GRID 296     // 148 SMs * 2 resident blocks

// ---------------- scratch ----------------------------------------------------
__device__ __align__(16) float  g_P[(size_t)Nn * 256];    // [N][256]: 0..127 src_p, 128..255 dst_p
__device__ __align__(16) float  g_acc[(size_t)Nn * 128];  // unnormalized aggregation
__device__ __align__(16) float2 g_md[(size_t)Nn * 8];     // per (node,head): (max, denom)
__device__ __align__(16) float  g_u[(size_t)Gg * 128];    // per-graph gated sum of out
__device__ __align__(16) float  g_gws[Gg];                // per-graph sum of gates
__device__ __align__(16) int    g_deg[Nn];                // zero-init; self-cleaned
__device__ __align__(16) int    g_off[Nn + 1];
__device__ __align__(16) int    g_cur[Nn];
__device__ __align__(16) int    g_srcidx[Ee];
__device__ int      g_flag[NBLK];
__device__ int      g_done;
__device__ unsigned g_maxenc;

#define FLAG_A (1 << 24)
#define FLAG_P (1 << 25)
#define VALMSK 0xFFFFFF

// ---------------- streams/events (created at static init, pre-baseline) ------
struct SideStream {
    cudaStream_t s = nullptr, s2 = nullptr;
    cudaEvent_t  e0 = nullptr, e1 = nullptr, e2 = nullptr;
    SideStream() {
        cudaStreamCreateWithFlags(&s,  cudaStreamNonBlocking);
        cudaStreamCreateWithFlags(&s2, cudaStreamNonBlocking);
        cudaEventCreateWithFlags(&e0, cudaEventDisableTiming);
        cudaEventCreateWithFlags(&e1, cudaEventDisableTiming);
        cudaEventCreateWithFlags(&e2, cudaEventDisableTiming);
    }
};
static SideStream g_ss;

// ---------------- f32x2 packed helpers ---------------------------------------
typedef unsigned long long u64;
__device__ __forceinline__ u64 p2(float lo, float hi) {
    u64 r;
    asm("mov.b64 %0, {%1, %2};" : "=l"(r) : "r"(__float_as_uint(lo)), "r"(__float_as_uint(hi)));
    return r;
}
__device__ __forceinline__ void fma2(u64& d, u64 a, u64 b) {
    asm("fma.rn.f32x2 %0, %1, %2, %3;" : "=l"(d) : "l"(a), "l"(b), "l"(d));
}
__device__ __forceinline__ float2 up2(u64 v) {
    unsigned lo, hi;
    asm("mov.b64 {%0, %1}, %2;" : "=r"(lo), "=r"(hi) : "l"(v));
    return make_float2(__uint_as_float(lo), __uint_as_float(hi));
}
__device__ __forceinline__ unsigned encf(float f) {
    unsigned u = __float_as_uint(f);
    return (u & 0x80000000u) ? ~u : (u | 0x80000000u);
}
__device__ __forceinline__ float decf(unsigned e) {
    unsigned u = (e & 0x80000000u) ? (e & 0x7fffffffu) : ~e;
    return __uint_as_float(u);
}

// ---------------- K0: degree histogram ---------------------------------------
__global__ void k_deg(const int* __restrict__ ei) {
    int e = blockIdx.x * blockDim.x + threadIdx.x;
    if (e < Ee) atomicAdd(&g_deg[ei[Ee + e]], 1);
}

// ---------------- K1: decoupled-lookback exclusive scan ----------------------
__global__ void k_scan() {
    int b = blockIdx.x, t = threadIdx.x;
    int i = b * 256 + t;
    int v = (i < Nn) ? g_deg[i] : 0;
    if (i < Nn) g_deg[i] = 0;
    if (b == 0 && t == 1) g_maxenc = 0u;
    int lane = t & 31, w = t >> 5;
    int incl = v;
#pragma unroll
    for (int o = 1; o < 32; o <<= 1) {
        int u = __shfl_up_sync(0xffffffffu, incl, o);
        if (lane >= o) incl += u;
    }
    __shared__ int wsum[8];
    if (lane == 31) wsum[w] = incl;
    __syncthreads();
    if (w == 0) {
        int z = (lane < 8) ? wsum[lane] : 0;
#pragma unroll
        for (int o = 1; o < 8; o <<= 1) {
            int u = __shfl_up_sync(0xffffffffu, z, o);
            if (lane >= o) z += u;
        }
        if (lane < 8) wsum[lane] = z;
    }
    __syncthreads();
    incl += (w ? wsum[w - 1] : 0);
    __shared__ int blksum_s, prev_s;
    if (t == 255) blksum_s = incl;
    __syncthreads();
    int blksum = blksum_s;
    if (t == 0) {
        int prev = 0;
        if (b == 0) {
            atomicExch(&g_flag[0], FLAG_P | blksum);
        } else {
            atomicExch(&g_flag[b], FLAG_A | blksum);
            int j = b - 1;
            while (true) {
                int f;
                do { f = *(volatile int*)&g_flag[j]; } while (f == 0);
                prev += f & VALMSK;
                if (f & FLAG_P) break;
                j--;
            }
            atomicExch(&g_flag[b], FLAG_P | (prev + blksum));
        }
        prev_s = prev;
    }
    __syncthreads();
    int excl = prev_s + incl - v;
    if (i < Nn) { g_off[i] = excl; g_cur[i] = excl; }
    if (b == NBLK - 1 && t == 255) g_off[Nn] = prev_s + incl;
    if (t == 0) {
        int d = atomicAdd(&g_done, 1);
        if (d == NBLK - 1) {
            for (int j = 0; j < NBLK; j++) g_flag[j] = 0;
            g_done = 0;
        }
    }
}

// ---------------- K2: scatter edges into CSR slots ---------------------------
__global__ void k_scatter(const int* __restrict__ ei) {
    int e = blockIdx.x * blockDim.x + threadIdx.x;
    if (e < Ee) {
        int d = ei[Ee + e];
        int pos = atomicAdd(&g_cur[d], 1);
        g_srcidx[pos] = ei[e];
    }
}

// ---------------- K3: P = x @ W^T — persistent grid-stride over tiles --------
__global__ void k_proj(const float* __restrict__ x,
                       const float* __restrict__ Wsrc,
                       const float* __restrict__ Wdst) {
    __shared__ __align__(16) float xs[2][8][128];
    __shared__ __align__(16) float ws[2][8][128];
    int t  = threadIdx.x;
    int tr = t >> 4, tc = t & 15;
    int lrow = t & 127, lk = (t >> 7) * 4;

    for (int tile = blockIdx.x; tile < PROJ_TILES; tile += gridDim.x) {
        int bx = tile % PROJ_BX;
        int m  = tile / PROJ_BX;
        const float* W = m ? Wdst : Wsrc;
        int rb = bx * 128;
        bool rowok = (rb + lrow) < Nn;
        const float* xrow = x + (size_t)(rb + lrow) * 128 + lk;
        const float* wrow = W + (size_t)lrow * 128 + lk;
        u64 acc[8][4];
#pragma unroll
        for (int i = 0; i < 8; i++)
#pragma unroll
            for (int j = 0; j < 4; j++) acc[i][j] = 0ull;

        __syncthreads();   // protect smem reuse across tiles
        {
            float4 xv4 = rowok ? *(const float4*)xrow : make_float4(0.f, 0.f, 0.f, 0.f);
            float4 wv4 = *(const float4*)wrow;
            xs[0][lk + 0][lrow] = xv4.x; xs[0][lk + 1][lrow] = xv4.y;
            xs[0][lk + 2][lrow] = xv4.z; xs[0][lk + 3][lrow] = xv4.w;
            ws[0][lk + 0][lrow] = wv4.x; ws[0][lk + 1][lrow] = wv4.y;
            ws[0][lk + 2][lrow] = wv4.z; ws[0][lk + 3][lrow] = wv4.w;
        }
        __syncthreads();
        int p = 0;
        for (int kc = 8; kc <= 128; kc += 8) {
            float4 nx, nw;
            bool more = kc < 128;
            if (more) {
                nx = rowok ? *(const float4*)(xrow + kc) : make_float4(0.f, 0.f, 0.f, 0.f);
                nw = *(const float4*)(wrow + kc);
            }
#pragma unroll
            for (int kk = 0; kk < 8; kk++) {
                float4 xa = *(const float4*)&xs[p][kk][tr * 4];
                float4 xb = *(const float4*)&xs[p][kk][64 + tr * 4];
                ulonglong2 wlo = *(const ulonglong2*)&ws[p][kk][tc * 4];
                ulonglong2 whi = *(const ulonglong2*)&ws[p][kk][64 + tc * 4];
                float xr0[4] = {xa.x, xa.y, xa.z, xa.w};
                float xr1[4] = {xb.x, xb.y, xb.z, xb.w};
#pragma unroll
                for (int i = 0; i < 4; i++) {
                    u64 xd = p2(xr0[i], xr0[i]);
                    fma2(acc[i][0], xd, wlo.x);
                    fma2(acc[i][1], xd, wlo.y);
                    fma2(acc[i][2], xd, whi.x);
                    fma2(acc[i][3], xd, whi.y);
                }
#pragma unroll
                for (int i = 0; i < 4; i++) {
                    u64 xd = p2(xr1[i], xr1[i]);
                    fma2(acc[4 + i][0], xd, wlo.x);
                    fma2(acc[4 + i][1], xd, wlo.y);
                    fma2(acc[4 + i][2], xd, whi.x);
                    fma2(acc[4 + i][3], xd, whi.y);
                }
            }
            if (more) {
                int q = p ^ 1;
                xs[q][lk + 0][lrow] = nx.x; xs[q][lk + 1][lrow] = nx.y;
                xs[q][lk + 2][lrow] = nx.z; xs[q][lk + 3][lrow] = nx.w;
                ws[q][lk + 0][lrow] = nw.x; ws[q][lk + 1][lrow] = nw.y;
                ws[q][lk + 2][lrow] = nw.z; ws[q][lk + 3][lrow] = nw.w;
                __syncthreads();
                p = q;
            }
        }
#pragma unroll
        for (int i = 0; i < 8; i++) {
            int row = rb + (i < 4 ? tr * 4 + i : 64 + tr * 4 + (i - 4));
            if (row < Nn) {
                ulonglong2 v0; v0.x = acc[i][0]; v0.y = acc[i][1];
                ulonglong2 v1; v1.x = acc[i][2]; v1.y = acc[i][3];
                *(ulonglong2*)&g_P[(size_t)row * 256 + m * 128 + tc * 4]      = v0;
                *(ulonglong2*)&g_P[(size_t)row * 256 + m * 128 + 64 + tc * 4] = v1;
            }
        }
    }
}

// ---------------- K4: fused logits + online-softmax aggregation --------------
// leaky(e) = 0.6e + 0.4|e|  =>  p = 0.6*(a.e) + 0.4*(a.|e|)  (operand-abs FFMA)
__global__ void k_edge(const float* __restrict__ attn) {
    int wid = (blockIdx.x * blockDim.x + threadIdx.x) >> 5;
    int l = threadIdx.x & 31;
    if (wid >= Nn) return;
    int n = wid;
    const float4 dp = *(const float4*)&g_P[(size_t)n * 256 + 128 + 4 * l];
    float a0 = attn[4 * l], a1 = attn[4 * l + 1], a2 = attn[4 * l + 2], a3 = attn[4 * l + 3];
    int beg = g_off[n], end = g_off[n + 1];
    float mh = -3.402823466e38f;
    float dh = 0.f;
    float4 acc = make_float4(0.f, 0.f, 0.f, 0.f);
    int i = beg;
    for (; i + 3 < end; i += 4) {
        int s0 = g_srcidx[i],     s1 = g_srcidx[i + 1];
        int s2 = g_srcidx[i + 2], s3 = g_srcidx[i + 3];
        float4 q0 = *(const float4*)&g_P[(size_t)s0 * 256 + 4 * l];
        float4 q1 = *(const float4*)&g_P[(size_t)s1 * 256 + 4 * l];
        float4 q2 = *(const float4*)&g_P[(size_t)s2 * 256 + 4 * l];
        float4 q3 = *(const float4*)&g_P[(size_t)s3 * 256 + 4 * l];
        float p0, p1, p2, p3;
        {
            float ex, ey, ez, ew, se, sa;
            ex = q0.x + dp.x; ey = q0.y + dp.y; ez = q0.z + dp.z; ew = q0.w + dp.w;
            se = a0 * ex + a1 * ey + a2 * ez + a3 * ew;
            sa = a0 * fabsf(ex) + a1 * fabsf(ey) + a2 * fabsf(ez) + a3 * fabsf(ew);
            p0 = 0.6f * se + 0.4f * sa;
            ex = q1.x + dp.x; ey = q1.y + dp.y; ez = q1.z + dp.z; ew = q1.w + dp.w;
            se = a0 * ex + a1 * ey + a2 * ez + a3 * ew;
            sa = a0 * fabsf(ex) + a1 * fabsf(ey) + a2 * fabsf(ez) + a3 * fabsf(ew);
            p1 = 0.6f * se + 0.4f * sa;
            ex = q2.x + dp.x; ey = q2.y + dp.y; ez = q2.z + dp.z; ew = q2.w + dp.w;
            se = a0 * ex + a1 * ey + a2 * ez + a3 * ew;
            sa = a0 * fabsf(ex) + a1 * fabsf(ey) + a2 * fabsf(ez) + a3 * fabsf(ew);
            p2 = 0.6f * se + 0.4f * sa;
            ex = q3.x + dp.x; ey = q3.y + dp.y; ez = q3.z + dp.z; ew = q3.w + dp.w;
            se = a0 * ex + a1 * ey + a2 * ez + a3 * ew;
            sa = a0 * fabsf(ex) + a1 * fabsf(ey) + a2 * fabsf(ez) + a3 * fabsf(ew);
            p3 = 0.6f * se + 0.4f * sa;
        }
        p0 += __shfl_xor_sync(0xffffffffu, p0, 1);
        p1 += __shfl_xor_sync(0xffffffffu, p1, 1);
        p2 += __shfl_xor_sync(0xffffffffu, p2, 1);
        p3 += __shfl_xor_sync(0xffffffffu, p3, 1);
        p0 += __shfl_xor_sync(0xffffffffu, p0, 2);
        p1 += __shfl_xor_sync(0xffffffffu, p1, 2);
        p2 += __shfl_xor_sync(0xffffffffu, p2, 2);
        p3 += __shfl_xor_sync(0xffffffffu, p3, 2);
        float gm = fmaxf(fmaxf(p0, p1), fmaxf(p2, p3));
        float nm = fmaxf(mh, gm);
        float r  = __expf(mh - nm);
        float w0 = __expf(p0 - nm), w1 = __expf(p1 - nm);
        float w2 = __expf(p2 - nm), w3 = __expf(p3 - nm);
        dh = dh * r + (w0 + w1 + w2 + w3);
        acc.x = acc.x * r + w0 * q0.x + w1 * q1.x + w2 * q2.x + w3 * q3.x;
        acc.y = acc.y * r + w0 * q0.y + w1 * q1.y + w2 * q2.y + w3 * q3.y;
        acc.z = acc.z * r + w0 * q0.z + w1 * q1.z + w2 * q2.z + w3 * q3.z;
        acc.w = acc.w * r + w0 * q0.w + w1 * q1.w + w2 * q2.w + w3 * q3.w;
        mh = nm;
    }
    for (; i < end; i++) {
        int s0 = g_srcidx[i];
        float4 q0 = *(const float4*)&g_P[(size_t)s0 * 256 + 4 * l];
        float ex = q0.x + dp.x, ey = q0.y + dp.y, ez = q0.z + dp.z, ew = q0.w + dp.w;
        float se = a0 * ex + a1 * ey + a2 * ez + a3 * ew;
        float sa = a0 * fabsf(ex) + a1 * fabsf(ey) + a2 * fabsf(ez) + a3 * fabsf(ew);
        float p0 = 0.6f * se + 0.4f * sa;
        p0 += __shfl_xor_sync(0xffffffffu, p0, 1);
        p0 += __shfl_xor_sync(0xffffffffu, p0, 2);
        float nm = fmaxf(mh, p0);
        float r  = __expf(mh - nm);
        float w0 = __expf(p0 - nm);
        dh = dh * r + w0;
        acc.x = acc.x * r + w0 * q0.x;
        acc.y = acc.y * r + w0 * q0.y;
        acc.z = acc.z * r + w0 * q0.z;
        acc.w = acc.w * r + w0 * q0.w;
        mh = nm;
    }
    *(float4*)&g_acc[(size_t)n * 128 + 4 * l] = acc;
    if ((l & 3) == 0) g_md[(size_t)n * 8 + (l >> 2)] = make_float2(mh, dh);
    if (beg < end) {
        float m = mh;
        for (int o = 16; o; o >>= 1) m = fmaxf(m, __shfl_xor_sync(0xffffffffu, m, o));
        if (l == 0) atomicMax(&g_maxenc, encf(m));
    }
}

// ---------------- K5: fused finalize + readout scan --------------------------
// computes out = PReLU(acc*f + x + bias), writes it, accumulates u_g/gws/max.
__global__ void k_rd3(const float* __restrict__ x, const int* __restrict__ batch,
                      const float* __restrict__ ww, const float* __restrict__ bw,
                      const float* __restrict__ bias, const float* __restrict__ prelu,
                      float* out) {
    __shared__ __align__(16) float redu[8 * 128];
    __shared__ __align__(16) float redm[8 * 128];
    __shared__ float gwss[8];
    __shared__ int bnds[2];
    int t = threadIdx.x, g = blockIdx.x;
    int w = t >> 5, l = t & 31;
    if (t < 2) {
        int tgt = g + t;
        int lo = 0, hi = Nn;
        while (lo < hi) {
            int mid = (lo + hi) >> 1;
            if (batch[mid] < tgt) lo = mid + 1; else hi = mid;
        }
        bnds[t] = lo;
    }
    __syncthreads();
    int beg = bnds[0], end = bnds[1];
    const float4 aw = *(const float4*)&ww[4 * l];
    const float4 bv = *(const float4*)&bias[4 * l];
    float bw0 = bw[0];
    float al  = prelu[0];
    float M   = decf(g_maxenc);
    float4 us = make_float4(0.f, 0.f, 0.f, 0.f);
    float4 mx = make_float4(-3.402823466e38f, -3.402823466e38f,
                            -3.402823466e38f, -3.402823466e38f);
    float gws = 0.f;
    for (int n = beg + w; n < end; n += 8) {
        float2 md = g_md[(size_t)n * 8 + (l >> 2)];
        float s = __expf(md.x - M);
        float f = s / (s * md.y + 1e-16f);
        float4 a4 = *(const float4*)&g_acc[(size_t)n * 128 + 4 * l];
        float4 x4 = *(const float4*)&x[(size_t)n * 128 + 4 * l];
        float4 o4;
        o4.x = a4.x * f + x4.x + bv.x; o4.x = o4.x > 0.f ? o4.x : al * o4.x;
        o4.y = a4.y * f + x4.y + bv.y; o4.y = o4.y > 0.f ? o4.y : al * o4.y;
        o4.z = a4.z * f + x4.z + bv.z; o4.z = o4.z > 0.f ? o4.z : al * o4.z;
        o4.w = a4.w * f + x4.w + bv.w; o4.w = o4.w > 0.f ? o4.w : al * o4.w;
        *(float4*)&out[(size_t)n * 128 + 4 * l] = o4;
        float v = o4.x * aw.x + o4.y * aw.y + o4.z * aw.z + o4.w * aw.w;
#pragma unroll
        for (int o = 16; o; o >>= 1) v += __shfl_xor_sync(0xffffffffu, v, o);
        float gw = 1.f / (1.f + __expf(-(v + bw0)));
        us.x += gw * o4.x; us.y += gw * o4.y;
        us.z += gw * o4.z; us.w += gw * o4.w;
        mx.x = fmaxf(mx.x, o4.x); mx.y = fmaxf(mx.y, o4.y);
        mx.z = fmaxf(mx.z, o4.z); mx.w = fmaxf(mx.w, o4.w);
        gws += gw;
    }
    *(float4*)&redu[w * 128 + 4 * l] = us;
    *(float4*)&redm[w * 128 + 4 * l] = mx;
    if (l == 0) gwss[w] = gws;
    __syncthreads();
    if (w == 0) {
        float4 tu = make_float4(0.f, 0.f, 0.f, 0.f);
        float4 tm = make_float4(-3.402823466e38f, -3.402823466e38f,
                                -3.402823466e38f, -3.402823466e38f);
#pragma unroll
        for (int r = 0; r < 8; r++) {
            float4 vu = *(const float4*)&redu[r * 128 + 4 * l];
            float4 vm = *(const float4*)&redm[r * 128 + 4 * l];
            tu.x += vu.x; tu.y += vu.y; tu.z += vu.z; tu.w += vu.w;
            tm.x = fmaxf(tm.x, vm.x); tm.y = fmaxf(tm.y, vm.y);
            tm.z = fmaxf(tm.z, vm.z); tm.w = fmaxf(tm.w, vm.w);
        }
        *(float4*)&g_u[(size_t)g * 128 + 4 * l] = tu;
        *(float4*)&out[(size_t)Nn * 128 + g * 256 + 128 + 4 * l] = tm;
        if (l == 0) {
            float s = 0.f;
#pragma unroll
            for (int r = 0; r < 8; r++) s += gwss[r];
            g_gws[g] = s;
        }
    }
}

// ---------------- K6: micro-GEMM g_sum = u @ Wsc^T + gws*bsc -----------------
__global__ void k_gsum(const float* __restrict__ Wsc, const float* __restrict__ bsc,
                       float* dout) {
    __shared__ __align__(16) float xs[2][8][128];
    __shared__ __align__(16) float ws[2][8][128];
    int t  = threadIdx.x;
    int tr = t >> 4, tc = t & 15;
    int rb = blockIdx.x * 128;
    int lrow = t & 127, lk = (t >> 7) * 4;
    const float* urow = g_u + (size_t)(rb + lrow) * 128 + lk;
    const float* wrow = Wsc + (size_t)lrow * 128 + lk;
    u64 acc[8][4];
#pragma unroll
    for (int i = 0; i < 8; i++)
#pragma unroll
        for (int j = 0; j < 4; j++) acc[i][j] = 0ull;

    {
        float4 xv4 = *(const float4*)urow;
        float4 wv4 = *(const float4*)wrow;
        xs[0][lk + 0][lrow] = xv4.x; xs[0][lk + 1][lrow] = xv4.y;
        xs[0][lk + 2][lrow] = xv4.z; xs[0][lk + 3][lrow] = xv4.w;
        ws[0][lk + 0][lrow] = wv4.x; ws[0][lk + 1][lrow] = wv4.y;
        ws[0][lk + 2][lrow] = wv4.z; ws[0][lk + 3][lrow] = wv4.w;
    }
    __syncthreads();
    int p = 0;
    for (int kc = 8; kc <= 128; kc += 8) {
        float4 nx, nw;
        bool more = kc < 128;
        if (more) {
            nx = *(const float4*)(urow + kc);
            nw = *(const float4*)(wrow + kc);
        }
#pragma unroll
        for (int kk = 0; kk < 8; kk++) {
            float4 xa = *(const float4*)&xs[p][kk][tr * 4];
            float4 xb = *(const float4*)&xs[p][kk][64 + tr * 4];
            ulonglong2 wlo = *(const ulonglong2*)&ws[p][kk][tc * 4];
            ulonglong2 whi = *(const ulonglong2*)&ws[p][kk][64 + tc * 4];
            float xr0[4] = {xa.x, xa.y, xa.z, xa.w};
            float xr1[4] = {xb.x, xb.y, xb.z, xb.w};
#pragma unroll
            for (int i = 0; i < 4; i++) {
                u64 xd = p2(xr0[i], xr0[i]);
                fma2(acc[i][0], xd, wlo.x);
                fma2(acc[i][1], xd, wlo.y);
                fma2(acc[i][2], xd, whi.x);
                fma2(acc[i][3], xd, whi.y);
            }
#pragma unroll
            for (int i = 0; i < 4; i++) {
                u64 xd = p2(xr1[i], xr1[i]);
                fma2(acc[4 + i][0], xd, wlo.x);
                fma2(acc[4 + i][1], xd, wlo.y);
                fma2(acc[4 + i][2], xd, whi.x);
                fma2(acc[4 + i][3], xd, whi.y);
            }
        }
        if (more) {
            int q = p ^ 1;
            xs[q][lk + 0][lrow] = nx.x; xs[q][lk + 1][lrow] = nx.y;
            xs[q][lk + 2][lrow] = nx.z; xs[q][lk + 3][lrow] = nx.w;
            ws[q][lk + 0][lrow] = nw.x; ws[q][lk + 1][lrow] = nw.y;
            ws[q][lk + 2][lrow] = nw.z; ws[q][lk + 3][lrow] = nw.w;
            __syncthreads();
            p = q;
        }
    }
#pragma unroll
    for (int i = 0; i < 8; i++) {
        int row = rb + (i < 4 ? tr * 4 + i : 64 + tr * 4 + (i - 4));   // graph id
        float gws = g_gws[row];
        float2 c0 = up2(acc[i][0]);
        float2 c1 = up2(acc[i][1]);
        float2 c2 = up2(acc[i][2]);
        float2 c3 = up2(acc[i][3]);
        int j0 = tc * 4, j1 = 64 + tc * 4;
        float4 b0 = *(const float4*)&bsc[j0];
        float4 b1 = *(const float4*)&bsc[j1];
        float4 o0 = make_float4(c0.x + gws * b0.x, c0.y + gws * b0.y,
                                c1.x + gws * b0.z, c1.y + gws * b0.w);
        float4 o1 = make_float4(c2.x + gws * b1.x, c2.y + gws * b1.y,
                                c3.x + gws * b1.z, c3.y + gws * b1.w);
        *(float4*)&dout[(size_t)Nn * 128 + (size_t)row * 256 + j0] = o0;
        *(float4*)&dout[(size_t)Nn * 128 + (size_t)row * 256 + j1] = o1;
    }
}

// ---------------- launch: fork-join DAG ---------------------------------------
// s : deg → scan → scatter ────────┐
// s2: proj ────────────────────────┴→ [0]: edge → rd3 → gsum
extern "C" void kernel_launch(void* const* d_in, const int* in_sizes, int n_in,
                              void* d_out, int out_size) {
    const float* x     = (const float*)d_in[0];
    const int*   ei    = (const int*)d_in[1];
    const int*   batch = (const int*)d_in[2];
    const float* Wsrc  = (const float*)d_in[3];
    const float* Wdst  = (const float*)d_in[4];
    const float* attn  = (const float*)d_in[5];
    const float* bias  = (const float*)d_in[6];
    const float* prelu = (const float*)d_in[7];
    const float* ww    = (const float*)d_in[8];
    const float* bw    = (const float*)d_in[9];
    const float* Wsc   = (const float*)d_in[10];
    const float* bsc   = (const float*)d_in[11];
    float*       out   = (float*)d_out;

    cudaEventRecord(g_ss.e0, 0);
    cudaStreamWaitEvent(g_ss.s,  g_ss.e0, 0);
    cudaStreamWaitEvent(g_ss.s2, g_ss.e0, 0);

    k_deg<<<(Ee + 511) / 512, 512, 0, g_ss.s>>>(ei);               // 0
    k_scan<<<NBLK, 256, 0, g_ss.s>>>();                            // 1
    k_scatter<<<(Ee + 511) / 512, 512, 0, g_ss.s>>>(ei);           // 2
    k_proj<<<PROJ_GRID, 256, 0, g_ss.s2>>>(x, Wsrc, Wdst);         // 3 <- ncu slot
    cudaEventRecord(g_ss.e1, g_ss.s);
    cudaEventRecord(g_ss.e2, g_ss.s2);
    cudaStreamWaitEvent(0, g_ss.e1, 0);
    cudaStreamWaitEvent(0, g_ss.e2, 0);

    k_edge<<<Nn / 8, 256>>>(attn);                                 // 4
    k_rd3<<<Gg, 256>>>(x, batch, ww, bw, bias, prelu, out);        // 5
    k_gsum<<<4, 256>>>(Wsc, bsc, out);                             // 6
}

// round 15
// speedup vs baseline: 1.1666x; 1.1666x over previous
#include <cuda_runtime.h>
#include <cstdint>

#define Nn 50000
#define Ee 800000
#define Gg 512
#define NBLK 196          // ceil(Nn/256)
#define PROJ_BX 391       // ceil(Nn/128)

// ---------------- scratch ----------------------------------------------------
__device__ __align__(16) float  g_P[(size_t)Nn * 256];    // [N][256]: 0..127 src_p, 128..255 dst_p
__device__ __align__(16) float  g_acc[(size_t)Nn * 128];  // unnormalized aggregation
__device__ __align__(16) float2 g_md[(size_t)Nn * 8];     // per (node,head): (max, denom)
__device__ __align__(16) float  g_u[(size_t)Gg * 128];    // per-graph gated sum of out
__device__ __align__(16) float  g_gws[Gg];                // per-graph sum of gates
__device__ __align__(16) int    g_deg[Nn];                // zero-init; self-cleaned
__device__ __align__(16) int    g_off[Nn + 1];
__device__ __align__(16) int    g_cur[Nn];
__device__ __align__(16) int    g_srcidx[Ee];
__device__ int      g_flag[NBLK];
__device__ int      g_done;
__device__ unsigned g_maxenc;

#define FLAG_A (1 << 24)
#define FLAG_P (1 << 25)
#define VALMSK 0xFFFFFF

// ---------------- streams/events (created at static init, pre-baseline) ------
struct SideStream {
    cudaStream_t s = nullptr, s2 = nullptr;
    cudaEvent_t  e0 = nullptr, e1 = nullptr, e2 = nullptr;
    SideStream() {
        cudaStreamCreateWithFlags(&s,  cudaStreamNonBlocking);
        cudaStreamCreateWithFlags(&s2, cudaStreamNonBlocking);
        cudaEventCreateWithFlags(&e0, cudaEventDisableTiming);
        cudaEventCreateWithFlags(&e1, cudaEventDisableTiming);
        cudaEventCreateWithFlags(&e2, cudaEventDisableTiming);
    }
};
static SideStream g_ss;

// ---------------- f32x2 packed helpers ---------------------------------------
typedef unsigned long long u64;
__device__ __forceinline__ u64 p2(float lo, float hi) {
    u64 r;
    asm("mov.b64 %0, {%1, %2};" : "=l"(r) : "r"(__float_as_uint(lo)), "r"(__float_as_uint(hi)));
    return r;
}
__device__ __forceinline__ void fma2(u64& d, u64 a, u64 b) {
    asm("fma.rn.f32x2 %0, %1, %2, %3;" : "=l"(d) : "l"(a), "l"(b), "l"(d));
}
__device__ __forceinline__ float2 up2(u64 v) {
    unsigned lo, hi;
    asm("mov.b64 {%0, %1}, %2;" : "=r"(lo), "=r"(hi) : "l"(v));
    return make_float2(__uint_as_float(lo), __uint_as_float(hi));
}
__device__ __forceinline__ unsigned encf(float f) {
    unsigned u = __float_as_uint(f);
    return (u & 0x80000000u) ? ~u : (u | 0x80000000u);
}
__device__ __forceinline__ float decf(unsigned e) {
    unsigned u = (e & 0x80000000u) ? (e & 0x7fffffffu) : ~e;
    return __uint_as_float(u);
}

// ---------------- K0: degree histogram ---------------------------------------
__global__ void k_deg(const int* __restrict__ ei) {
    int e = blockIdx.x * blockDim.x + threadIdx.x;
    if (e < Ee) atomicAdd(&g_deg[ei[Ee + e]], 1);
}

// ---------------- K1: decoupled-lookback exclusive scan ----------------------
__global__ void k_scan() {
    int b = blockIdx.x, t = threadIdx.x;
    int i = b * 256 + t;
    int v = (i < Nn) ? g_deg[i] : 0;
    if (i < Nn) g_deg[i] = 0;
    if (b == 0 && t == 1) g_maxenc = 0u;
    int lane = t & 31, w = t >> 5;
    int incl = v;
#pragma unroll
    for (int o = 1; o < 32; o <<= 1) {
        int u = __shfl_up_sync(0xffffffffu, incl, o);
        if (lane >= o) incl += u;
    }
    __shared__ int wsum[8];
    if (lane == 31) wsum[w] = incl;
    __syncthreads();
    if (w == 0) {
        int z = (lane < 8) ? wsum[lane] : 0;
#pragma unroll
        for (int o = 1; o < 8; o <<= 1) {
            int u = __shfl_up_sync(0xffffffffu, z, o);
            if (lane >= o) z += u;
        }
        if (lane < 8) wsum[lane] = z;
    }
    __syncthreads();
    incl += (w ? wsum[w - 1] : 0);
    __shared__ int blksum_s, prev_s;
    if (t == 255) blksum_s = incl;
    __syncthreads();
    int blksum = blksum_s;
    if (t == 0) {
        int prev = 0;
        if (b == 0) {
            atomicExch(&g_flag[0], FLAG_P | blksum);
        } else {
            atomicExch(&g_flag[b], FLAG_A | blksum);
            int j = b - 1;
            while (true) {
                int f;
                do { f = *(volatile int*)&g_flag[j]; } while (f == 0);
                prev += f & VALMSK;
                if (f & FLAG_P) break;
                j--;
            }
            atomicExch(&g_flag[b], FLAG_P | (prev + blksum));
        }
        prev_s = prev;
    }
    __syncthreads();
    int excl = prev_s + incl - v;
    if (i < Nn) { g_off[i] = excl; g_cur[i] = excl; }
    if (b == NBLK - 1 && t == 255) g_off[Nn] = prev_s + incl;
    if (t == 0) {
        int d = atomicAdd(&g_done, 1);
        if (d == NBLK - 1) {
            for (int j = 0; j < NBLK; j++) g_flag[j] = 0;
            g_done = 0;
        }
    }
}

// ---------------- K2: scatter edges into CSR slots ---------------------------
__global__ void k_scatter(const int* __restrict__ ei) {
    int e = blockIdx.x * blockDim.x + threadIdx.x;
    if (e < Ee) {
        int d = ei[Ee + e];
        int pos = atomicAdd(&g_cur[d], 1);
        g_srcidx[pos] = ei[e];
    }
}

// ---------------- K3: P = x @ W^T, 128x128 tile, conflict-free split tile ----
__global__ void k_proj(const float* __restrict__ x,
                       const float* __restrict__ Wsrc,
                       const float* __restrict__ Wdst) {
    __shared__ __align__(16) float xs[2][8][128];
    __shared__ __align__(16) float ws[2][8][128];
    int m = blockIdx.y;
    const float* W = m ? Wdst : Wsrc;
    int t  = threadIdx.x;
    int tr = t >> 4, tc = t & 15;
    int rb = blockIdx.x * 128;
    int lrow = t & 127, lk = (t >> 7) * 4;
    bool rowok = (rb + lrow) < Nn;
    const float* xrow = x + (size_t)(rb + lrow) * 128 + lk;
    const float* wrow = W + (size_t)lrow * 128 + lk;
    u64 acc[8][4];
#pragma unroll
    for (int i = 0; i < 8; i++)
#pragma unroll
        for (int j = 0; j < 4; j++) acc[i][j] = 0ull;

    {
        float4 xv4 = rowok ? *(const float4*)xrow : make_float4(0.f, 0.f, 0.f, 0.f);
        float4 wv4 = *(const float4*)wrow;
        xs[0][lk + 0][lrow] = xv4.x; xs[0][lk + 1][lrow] = xv4.y;
        xs[0][lk + 2][lrow] = xv4.z; xs[0][lk + 3][lrow] = xv4.w;
        ws[0][lk + 0][lrow] = wv4.x; ws[0][lk + 1][lrow] = wv4.y;
        ws[0][lk + 2][lrow] = wv4.z; ws[0][lk + 3][lrow] = wv4.w;
    }
    __syncthreads();
    int p = 0;
    for (int kc = 8; kc <= 128; kc += 8) {
        float4 nx, nw;
        bool more = kc < 128;
        if (more) {
            nx = rowok ? *(const float4*)(xrow + kc) : make_float4(0.f, 0.f, 0.f, 0.f);
            nw = *(const float4*)(wrow + kc);
        }
#pragma unroll
        for (int kk = 0; kk < 8; kk++) {
            float4 xa = *(const float4*)&xs[p][kk][tr * 4];
            float4 xb = *(const float4*)&xs[p][kk][64 + tr * 4];
            ulonglong2 wlo = *(const ulonglong2*)&ws[p][kk][tc * 4];
            ulonglong2 whi = *(const ulonglong2*)&ws[p][kk][64 + tc * 4];
            float xr0[4] = {xa.x, xa.y, xa.z, xa.w};
            float xr1[4] = {xb.x, xb.y, xb.z, xb.w};
#pragma unroll
            for (int i = 0; i < 4; i++) {
                u64 xd = p2(xr0[i], xr0[i]);
                fma2(acc[i][0], xd, wlo.x);
                fma2(acc[i][1], xd, wlo.y);
                fma2(acc[i][2], xd, whi.x);
                fma2(acc[i][3], xd, whi.y);
            }
#pragma unroll
            for (int i = 0; i < 4; i++) {
                u64 xd = p2(xr1[i], xr1[i]);
                fma2(acc[4 + i][0], xd, wlo.x);
                fma2(acc[4 + i][1], xd, wlo.y);
                fma2(acc[4 + i][2], xd, whi.x);
                fma2(acc[4 + i][3], xd, whi.y);
            }
        }
        if (more) {
            int q = p ^ 1;
            xs[q][lk + 0][lrow] = nx.x; xs[q][lk + 1][lrow] = nx.y;
            xs[q][lk + 2][lrow] = nx.z; xs[q][lk + 3][lrow] = nx.w;
            ws[q][lk + 0][lrow] = nw.x; ws[q][lk + 1][lrow] = nw.y;
            ws[q][lk + 2][lrow] = nw.z; ws[q][lk + 3][lrow] = nw.w;
            __syncthreads();
            p = q;
        }
    }
#pragma unroll
    for (int i = 0; i < 8; i++) {
        int row = rb + (i < 4 ? tr * 4 + i : 64 + tr * 4 + (i - 4));
        if (row < Nn) {
            ulonglong2 v0; v0.x = acc[i][0]; v0.y = acc[i][1];
            ulonglong2 v1; v1.x = acc[i][2]; v1.y = acc[i][3];
            *(ulonglong2*)&g_P[(size_t)row * 256 + m * 128 + tc * 4]      = v0;
            *(ulonglong2*)&g_P[(size_t)row * 256 + m * 128 + 64 + tc * 4] = v1;
        }
    }
}

// ---------------- K4: fused logits + online-softmax aggregation --------------
// leaky(e) = 0.6e + 0.4|e|  =>  p = 0.6*(a.e) + 0.4*(a.|e|)
__global__ void k_edge(const float* __restrict__ attn) {
    int wid = (blockIdx.x * blockDim.x + threadIdx.x) >> 5;
    int l = threadIdx.x & 31;
    if (wid >= Nn) return;
    int n = wid;
    const float4 dp = *(const float4*)&g_P[(size_t)n * 256 + 128 + 4 * l];
    float a0 = attn[4 * l], a1 = attn[4 * l + 1], a2 = attn[4 * l + 2], a3 = attn[4 * l + 3];
    int beg = g_off[n], end = g_off[n + 1];
    float mh = -3.402823466e38f;
    float dh = 0.f;
    float4 acc = make_float4(0.f, 0.f, 0.f, 0.f);
    int i = beg;
    for (; i + 3 < end; i += 4) {
        int s0 = g_srcidx[i],     s1 = g_srcidx[i + 1];
        int s2 = g_srcidx[i + 2], s3 = g_srcidx[i + 3];
        float4 q0 = *(const float4*)&g_P[(size_t)s0 * 256 + 4 * l];
        float4 q1 = *(const float4*)&g_P[(size_t)s1 * 256 + 4 * l];
        float4 q2 = *(const float4*)&g_P[(size_t)s2 * 256 + 4 * l];
        float4 q3 = *(const float4*)&g_P[(size_t)s3 * 256 + 4 * l];
        float p0, p1, p2, p3;
        {
            float ex, ey, ez, ew, se, sa;
            ex = q0.x + dp.x; ey = q0.y + dp.y; ez = q0.z + dp.z; ew = q0.w + dp.w;
            se = a0 * ex + a1 * ey + a2 * ez + a3 * ew;
            sa = a0 * fabsf(ex) + a1 * fabsf(ey) + a2 * fabsf(ez) + a3 * fabsf(ew);
            p0 = 0.6f * se + 0.4f * sa;
            ex = q1.x + dp.x; ey = q1.y + dp.y; ez = q1.z + dp.z; ew = q1.w + dp.w;
            se = a0 * ex + a1 * ey + a2 * ez + a3 * ew;
            sa = a0 * fabsf(ex) + a1 * fabsf(ey) + a2 * fabsf(ez) + a3 * fabsf(ew);
            p1 = 0.6f * se + 0.4f * sa;
            ex = q2.x + dp.x; ey = q2.y + dp.y; ez = q2.z + dp.z; ew = q2.w + dp.w;
            se = a0 * ex + a1 * ey + a2 * ez + a3 * ew;
            sa = a0 * fabsf(ex) + a1 * fabsf(ey) + a2 * fabsf(ez) + a3 * fabsf(ew);
            p2 = 0.6f * se + 0.4f * sa;
            ex = q3.x + dp.x; ey = q3.y + dp.y; ez = q3.z + dp.z; ew = q3.w + dp.w;
            se = a0 * ex + a1 * ey + a2 * ez + a3 * ew;
            sa = a0 * fabsf(ex) + a1 * fabsf(ey) + a2 * fabsf(ez) + a3 * fabsf(ew);
            p3 = 0.6f * se + 0.4f * sa;
        }
        p0 += __shfl_xor_sync(0xffffffffu, p0, 1);
        p1 += __shfl_xor_sync(0xffffffffu, p1, 1);
        p2 += __shfl_xor_sync(0xffffffffu, p2, 1);
        p3 += __shfl_xor_sync(0xffffffffu, p3, 1);
        p0 += __shfl_xor_sync(0xffffffffu, p0, 2);
        p1 += __shfl_xor_sync(0xffffffffu, p1, 2);
        p2 += __shfl_xor_sync(0xffffffffu, p2, 2);
        p3 += __shfl_xor_sync(0xffffffffu, p3, 2);
        float gm = fmaxf(fmaxf(p0, p1), fmaxf(p2, p3));
        float nm = fmaxf(mh, gm);
        float r  = __expf(mh - nm);
        float w0 = __expf(p0 - nm), w1 = __expf(p1 - nm);
        float w2 = __expf(p2 - nm), w3 = __expf(p3 - nm);
        dh = dh * r + (w0 + w1 + w2 + w3);
        acc.x = acc.x * r + w0 * q0.x + w1 * q1.x + w2 * q2.x + w3 * q3.x;
        acc.y = acc.y * r + w0 * q0.y + w1 * q1.y + w2 * q2.y + w3 * q3.y;
        acc.z = acc.z * r + w0 * q0.z + w1 * q1.z + w2 * q2.z + w3 * q3.z;
        acc.w = acc.w * r + w0 * q0.w + w1 * q1.w + w2 * q2.w + w3 * q3.w;
        mh = nm;
    }
    for (; i < end; i++) {
        int s0 = g_srcidx[i];
        float4 q0 = *(const float4*)&g_P[(size_t)s0 * 256 + 4 * l];
        float ex = q0.x + dp.x, ey = q0.y + dp.y, ez = q0.z + dp.z, ew = q0.w + dp.w;
        float se = a0 * ex + a1 * ey + a2 * ez + a3 * ew;
        float sa = a0 * fabsf(ex) + a1 * fabsf(ey) + a2 * fabsf(ez) + a3 * fabsf(ew);
        float p0 = 0.6f * se + 0.4f * sa;
        p0 += __shfl_xor_sync(0xffffffffu, p0, 1);
        p0 += __shfl_xor_sync(0xffffffffu, p0, 2);
        float nm = fmaxf(mh, p0);
        float r  = __expf(mh - nm);
        float w0 = __expf(p0 - nm);
        dh = dh * r + w0;
        acc.x = acc.x * r + w0 * q0.x;
        acc.y = acc.y * r + w0 * q0.y;
        acc.z = acc.z * r + w0 * q0.z;
        acc.w = acc.w * r + w0 * q0.w;
        mh = nm;
    }
    *(float4*)&g_acc[(size_t)n * 128 + 4 * l] = acc;
    if ((l & 3) == 0) g_md[(size_t)n * 8 + (l >> 2)] = make_float2(mh, dh);
    if (beg < end) {
        float m = mh;
        for (int o = 16; o; o >>= 1) m = fmaxf(m, __shfl_xor_sync(0xffffffffu, m, o));
        if (l == 0) atomicMax(&g_maxenc, encf(m));
    }
}

// ---------------- K5: finalize — normalize + residual + PReLU ----------------
__global__ void k_fin(const float* __restrict__ x, const float* __restrict__ bias,
                      const float* __restrict__ prelu, float* out) {
    int wid = (blockIdx.x * blockDim.x + threadIdx.x) >> 5;
    int l = threadIdx.x & 31;
    if (wid >= Nn) return;
    int n = wid;
    float M = decf(g_maxenc);
    float2 md = g_md[(size_t)n * 8 + (l >> 2)];
    float s = __expf(md.x - M);
    float f = s / (s * md.y + 1e-16f);
    float4 a4 = *(const float4*)&g_acc[(size_t)n * 128 + 4 * l];
    const float4 xv = *(const float4*)&x[(size_t)n * 128 + 4 * l];
    const float4 bv = *(const float4*)&bias[4 * l];
    float al = prelu[0];
    float o0 = a4.x * f + xv.x + bv.x; o0 = o0 > 0.f ? o0 : al * o0;
    float o1 = a4.y * f + xv.y + bv.y; o1 = o1 > 0.f ? o1 : al * o1;
    float o2 = a4.z * f + xv.z + bv.z; o2 = o2 > 0.f ? o2 : al * o2;
    float o3 = a4.w * f + xv.w + bv.w; o3 = o3 > 0.f ? o3 : al * o3;
    *(float4*)&out[(size_t)n * 128 + 4 * l] = make_float4(o0, o1, o2, o3);
}

// ---------------- K6: readout scan — gates, u_g, gws, max-pool ---------------
__global__ void k_rd3(const float* __restrict__ out, const int* __restrict__ batch,
                      const float* __restrict__ ww, const float* __restrict__ bw,
                      float* dout) {
    __shared__ __align__(16) float redu[8 * 128];
    __shared__ __align__(16) float redm[8 * 128];
    __shared__ float gwss[8];
    __shared__ int bnds[2];
    int t = threadIdx.x, g = blockIdx.x;
    int w = t >> 5, l = t & 31;
    if (t < 2) {
        int tgt = g + t;
        int lo = 0, hi = Nn;
        while (lo < hi) {
            int mid = (lo + hi) >> 1;
            if (batch[mid] < tgt) lo = mid + 1; else hi = mid;
        }
        bnds[t] = lo;
    }
    __syncthreads();
    int beg = bnds[0], end = bnds[1];
    const float4 aw = *(const float4*)&ww[4 * l];
    float bw0 = bw[0];
    float4 us = make_float4(0.f, 0.f, 0.f, 0.f);
    float4 mx = make_float4(-3.402823466e38f, -3.402823466e38f,
                            -3.402823466e38f, -3.402823466e38f);
    float gws = 0.f;
    for (int n = beg + w; n < end; n += 8) {
        float4 o4 = *(const float4*)&out[(size_t)n * 128 + 4 * l];
        float v = o4.x * aw.x + o4.y * aw.y + o4.z * aw.z + o4.w * aw.w;
#pragma unroll
        for (int o = 16; o; o >>= 1) v += __shfl_xor_sync(0xffffffffu, v, o);
        float gw = 1.f / (1.f + __expf(-(v + bw0)));
        us.x += gw * o4.x; us.y += gw * o4.y;
        us.z += gw * o4.z; us.w += gw * o4.w;
        mx.x = fmaxf(mx.x, o4.x); mx.y = fmaxf(mx.y, o4.y);
        mx.z = fmaxf(mx.z, o4.z); mx.w = fmaxf(mx.w, o4.w);
        gws += gw;
    }
    *(float4*)&redu[w * 128 + 4 * l] = us;
    *(float4*)&redm[w * 128 + 4 * l] = mx;
    if (l == 0) gwss[w] = gws;
    __syncthreads();
    if (w == 0) {
        float4 tu = make_float4(0.f, 0.f, 0.f, 0.f);
        float4 tm = make_float4(-3.402823466e38f, -3.402823466e38f,
                                -3.402823466e38f, -3.402823466e38f);
#pragma unroll
        for (int r = 0; r < 8; r++) {
            float4 vu = *(const float4*)&redu[r * 128 + 4 * l];
            float4 vm = *(const float4*)&redm[r * 128 + 4 * l];
            tu.x += vu.x; tu.y += vu.y; tu.z += vu.z; tu.w += vu.w;
            tm.x = fmaxf(tm.x, vm.x); tm.y = fmaxf(tm.y, vm.y);
            tm.z = fmaxf(tm.z, vm.z); tm.w = fmaxf(tm.w, vm.w);
        }
        *(float4*)&g_u[(size_t)g * 128 + 4 * l] = tu;
        *(float4*)&dout[(size_t)Nn * 128 + g * 256 + 128 + 4 * l] = tm;
        if (l == 0) {
            float s = 0.f;
#pragma unroll
            for (int r = 0; r < 8; r++) s += gwss[r];
            g_gws[g] = s;
        }
    }
}

// ---------------- K7: micro-GEMM g_sum = u @ Wsc^T + gws*bsc -----------------
__global__ void k_gsum(const float* __restrict__ Wsc, const float* __restrict__ bsc,
                       float* dout) {
    __shared__ __align__(16) float xs[2][8][128];
    __shared__ __align__(16) float ws[2][8][128];
    int t  = threadIdx.x;
    int tr = t >> 4, tc = t & 15;
    int rb = blockIdx.x * 128;
    int lrow = t & 127, lk = (t >> 7) * 4;
    const float* urow = g_u + (size_t)(rb + lrow) * 128 + lk;
    const float* wrow = Wsc + (size_t)lrow * 128 + lk;
    u64 acc[8][4];
#pragma unroll
    for (int i = 0; i < 8; i++)
#pragma unroll
        for (int j = 0; j < 4; j++) acc[i][j] = 0ull;

    {
        float4 xv4 = *(const float4*)urow;
        float4 wv4 = *(const float4*)wrow;
        xs[0][lk + 0][lrow] = xv4.x; xs[0][lk + 1][lrow] = xv4.y;
        xs[0][lk + 2][lrow] = xv4.z; xs[0][lk + 3][lrow] = xv4.w;
        ws[0][lk + 0][lrow] = wv4.x; ws[0][lk + 1][lrow] = wv4.y;
        ws[0][lk + 2][lrow] = wv4.z; ws[0][lk + 3][lrow] = wv4.w;
    }
    __syncthreads();
    int p = 0;
    for (int kc = 8; kc <= 128; kc += 8) {
        float4 nx, nw;
        bool more = kc < 128;
        if (more) {
            nx = *(const float4*)(urow + kc);
            nw = *(const float4*)(wrow + kc);
        }
#pragma unroll
        for (int kk = 0; kk < 8; kk++) {
            float4 xa = *(const float4*)&xs[p][kk][tr * 4];
            float4 xb = *(const float4*)&xs[p][kk][64 + tr * 4];
            ulonglong2 wlo = *(const ulonglong2*)&ws[p][kk][tc * 4];
            ulonglong2 whi = *(const ulonglong2*)&ws[p][kk][64 + tc * 4];
            float xr0[4] = {xa.x, xa.y, xa.z, xa.w};
            float xr1[4] = {xb.x, xb.y, xb.z, xb.w};
#pragma unroll
            for (int i = 0; i < 4; i++) {
                u64 xd = p2(xr0[i], xr0[i]);
                fma2(acc[i][0], xd, wlo.x);
                fma2(acc[i][1], xd, wlo.y);
                fma2(acc[i][2], xd, whi.x);
                fma2(acc[i][3], xd, whi.y);
            }
#pragma unroll
            for (int i = 0; i < 4; i++) {
                u64 xd = p2(xr1[i], xr1[i]);
                fma2(acc[4 + i][0], xd, wlo.x);
                fma2(acc[4 + i][1], xd, wlo.y);
                fma2(acc[4 + i][2], xd, whi.x);
                fma2(acc[4 + i][3], xd, whi.y);
            }
        }
        if (more) {
            int q = p ^ 1;
            xs[q][lk + 0][lrow] = nx.x; xs[q][lk + 1][lrow] = nx.y;
            xs[q][lk + 2][lrow] = nx.z; xs[q][lk + 3][lrow] = nx.w;
            ws[q][lk + 0][lrow] = nw.x; ws[q][lk + 1][lrow] = nw.y;
            ws[q][lk + 2][lrow] = nw.z; ws[q][lk + 3][lrow] = nw.w;
            __syncthreads();
            p = q;
        }
    }
#pragma unroll
    for (int i = 0; i < 8; i++) {
        int row = rb + (i < 4 ? tr * 4 + i : 64 + tr * 4 + (i - 4));   // graph id
        float gws = g_gws[row];
        float2 c0 = up2(acc[i][0]);
        float2 c1 = up2(acc[i][1]);
        float2 c2 = up2(acc[i][2]);
        float2 c3 = up2(acc[i][3]);
        int j0 = tc * 4, j1 = 64 + tc * 4;
        float4 b0 = *(const float4*)&bsc[j0];
        float4 b1 = *(const float4*)&bsc[j1];
        float4 o0 = make_float4(c0.x + gws * b0.x, c0.y + gws * b0.y,
                                c1.x + gws * b0.z, c1.y + gws * b0.w);
        float4 o1 = make_float4(c2.x + gws * b1.x, c2.y + gws * b1.y,
                                c3.x + gws * b1.z, c3.y + gws * b1.w);
        *(float4*)&dout[(size_t)Nn * 128 + (size_t)row * 256 + j0] = o0;
        *(float4*)&dout[(size_t)Nn * 128 + (size_t)row * 256 + j1] = o1;
    }
}

// ---------------- launch: fork-join DAG ---------------------------------------
// s : deg → scan → scatter ────────┐
// s2: proj ────────────────────────┴→ [0]: edge → fin → rd3 → gsum
extern "C" void kernel_launch(void* const* d_in, const int* in_sizes, int n_in,
                              void* d_out, int out_size) {
    const float* x     = (const float*)d_in[0];
    const int*   ei    = (const int*)d_in[1];
    const int*   batch = (const int*)d_in[2];
    const float* Wsrc  = (const float*)d_in[3];
    const float* Wdst  = (const float*)d_in[4];
    const float* attn  = (const float*)d_in[5];
    const float* bias  = (const float*)d_in[6];
    const float* prelu = (const float*)d_in[7];
    const float* ww    = (const float*)d_in[8];
    const float* bw    = (const float*)d_in[9];
    const float* Wsc   = (const float*)d_in[10];
    const float* bsc   = (const float*)d_in[11];
    float*       out   = (float*)d_out;

    cudaEventRecord(g_ss.e0, 0);
    cudaStreamWaitEvent(g_ss.s,  g_ss.e0, 0);
    cudaStreamWaitEvent(g_ss.s2, g_ss.e0, 0);

    k_deg<<<(Ee + 511) / 512, 512, 0, g_ss.s>>>(ei);               // 0
    k_scan<<<NBLK, 256, 0, g_ss.s>>>();                            // 1
    k_scatter<<<(Ee + 511) / 512, 512, 0, g_ss.s>>>(ei);           // 2
    dim3 gp(PROJ_BX, 2);
    k_proj<<<gp, 256, 0, g_ss.s2>>>(x, Wsrc, Wdst);                // 3 <- ncu slot
    cudaEventRecord(g_ss.e1, g_ss.s);
    cudaEventRecord(g_ss.e2, g_ss.s2);
    cudaStreamWaitEvent(0, g_ss.e1, 0);
    cudaStreamWaitEvent(0, g_ss.e2, 0);

    k_edge<<<Nn / 8, 256>>>(attn);                                 // 4
    k_fin<<<Nn / 8, 256>>>(x, bias, prelu, out);                   // 5
    k_rd3<<<Gg, 256>>>(out, batch, ww, bw, out);                   // 6
    k_gsum<<<4, 256>>>(Wsc, bsc, out);                             // 7
}